// round 12
// baseline (speedup 1.0000x reference)
#include <cuda_runtime.h>
#include <cuda_bf16.h>
#include <cstdint>

typedef unsigned long long u64;
typedef unsigned int u32;

#define NB 16
#define NT 96
#define NN 325
#define ND 64
#define NH 64
#define NROWS (NB*NN)          // 5200
#define BTN (NB*NT*NN)         // 499200
#define HSTRIDE (NN*NH)        // 20800
#define BSTRIDE (NT*NN*NH)     // 1996800

// Fused scratch: [t][row][384] with row = b*NN+n; cols: f,i,o,u,gf,gu (64 each)
__device__ float g_AG[(size_t)BTN * 384];

// ================= helpers =================
__device__ __forceinline__ u32 smem_u32(const void* p){
    u32 a; asm("{ .reg .u64 t; cvta.to.shared.u64 t, %1; cvt.u32.u64 %0, t; }" : "=r"(a) : "l"(p));
    return a;
}
__device__ __forceinline__ u32 bfpack(float lo_elem, float hi_elem){
    u32 r; asm("cvt.rn.bf16x2.f32 %0, %1, %2;" : "=r"(r) : "f"(hi_elem), "f"(lo_elem));
    return r;
}
__device__ __forceinline__ void ldsm_x4(u32& a0,u32& a1,u32& a2,u32& a3, u32 addr){
    asm volatile("ldmatrix.sync.aligned.m8n8.x4.shared.b16 {%0,%1,%2,%3}, [%4];"
      : "=r"(a0),"=r"(a1),"=r"(a2),"=r"(a3) : "r"(addr));
}
__device__ __forceinline__ void ldsm_x2(u32& b0,u32& b1, u32 addr){
    asm volatile("ldmatrix.sync.aligned.m8n8.x2.shared.b16 {%0,%1}, [%2];"
      : "=r"(b0),"=r"(b1) : "r"(addr));
}
__device__ __forceinline__ void mma16816(float* c, const u32* a, const u32* b){
    asm volatile("mma.sync.aligned.m16n8k16.row.col.f32.bf16.bf16.f32 "
      "{%0,%1,%2,%3}, {%4,%5,%6,%7}, {%8,%9}, {%0,%1,%2,%3};"
      : "+f"(c[0]),"+f"(c[1]),"+f"(c[2]),"+f"(c[3])
      : "r"(a[0]),"r"(a[1]),"r"(a[2]),"r"(a[3]), "r"(b[0]),"r"(b[1]));
}

// =====================================================================
// Phase 1 (HMMA, proven R7-R11): per 64-row tile fused [xUx+bx | oUg+bg]
// (N=384), split-3 bf16, register prefetch pipelining.
// =====================================================================
#define P1_THREADS 256
#define P1_ROWS 64
#define P1_TILES (BTN/P1_ROWS)   // 7800
#define P1_GRID 148

#define PITCH 400
#define S_BIAS 0
#define S_B    1536
#define S_AX   155136
#define S_AO   180736
#define P1_SMEM 206336

__global__ void __launch_bounds__(P1_THREADS, 1)
glstm_pre_mma(const float* __restrict__ x, const float* __restrict__ osrc,
              const float* __restrict__ Ux, const float* __restrict__ bx,
              const float* __restrict__ Ug, const float* __restrict__ bg)
{
    extern __shared__ unsigned char smem[];
    float* bias_s = (float*)(smem + S_BIAS);
    const int tid = threadIdx.x;
    const int w   = tid >> 5;
    const int lane = tid & 31;
    const int gid = lane >> 2, tid4 = lane & 3;

    bias_s[tid] = bx[tid];
    if (tid < 128) bias_s[256 + tid] = bg[tid];

    for (int i = tid; i < 64*256; i += P1_THREADS){
        int n = i & 255, k = i >> 8;
        float v = Ux[k*256 + n];
        __nv_bfloat16 hb = __float2bfloat16(v);
        float lo = v - __bfloat162float(hb);
        __nv_bfloat16* row = (__nv_bfloat16*)(smem + S_B + n*PITCH);
        row[k] = hb; row[128 + k] = hb;
        row[64 + k] = __float2bfloat16(lo);
    }
    for (int i = tid; i < 64*128; i += P1_THREADS){
        int n = i & 127, k = i >> 7;
        float v = Ug[k*128 + n];
        __nv_bfloat16 hb = __float2bfloat16(v);
        float lo = v - __bfloat162float(hb);
        __nv_bfloat16* row = (__nv_bfloat16*)(smem + S_B + (256 + n)*PITCH);
        row[k] = hb; row[128 + k] = hb;
        row[64 + k] = __float2bfloat16(lo);
    }

    const u32 sb = smem_u32(smem);
    u32 rowAx[4], rowAo[4];
    #pragma unroll
    for (int mi = 0; mi < 4; mi++){
        u32 off = (u32)(16*mi + (lane & 15))*PITCH + ((lane >> 4) << 4);
        rowAx[mi] = sb + S_AX + off;
        rowAo[mi] = sb + S_AO + off;
    }
    u32 rowB[6];
    #pragma unroll
    for (int ni = 0; ni < 6; ni++)
        rowB[ni] = sb + S_B + (u32)(48*w + 8*ni + (lane & 7))*PITCH + (((lane >> 3) & 1) << 4);

    const bool needx = (w <= 5), needo = (w >= 5);

    const int cr = tid >> 2, ck0 = (tid & 3) << 4;
    u32* ax32 = (u32*)(smem + S_AX + cr*PITCH);
    u32* ao32 = (u32*)(smem + S_AO + cr*PITCH);

    int tile = blockIdx.x;
    float4 xv[4], ov[4];
    {
        const float4* xp = (const float4*)(x    + (size_t)((long long)tile*P1_ROWS + cr)*64 + ck0);
        const float4* op = (const float4*)(osrc + (size_t)((long long)tile*P1_ROWS + cr)*64 + ck0);
        #pragma unroll
        for (int j = 0; j < 4; j++){ xv[j] = xp[j]; ov[j] = op[j]; }
    }

    while (tile < P1_TILES){
        const long long m0 = (long long)tile * P1_ROWS;

        #pragma unroll
        for (int j = 0; j < 4; j++){
            #pragma unroll
            for (int h = 0; h < 2; h++){
                float a = h ? xv[j].z : xv[j].x;
                float b = h ? xv[j].w : xv[j].y;
                int k = ck0 + 4*j + 2*h;
                u32 hp = bfpack(a, b);
                float ra = a - __uint_as_float(hp << 16);
                float rb = b - __uint_as_float(hp & 0xFFFF0000u);
                u32 lp = bfpack(ra, rb);
                ax32[k>>1] = hp; ax32[32 + (k>>1)] = hp; ax32[64 + (k>>1)] = lp;

                a = h ? ov[j].z : ov[j].x;
                b = h ? ov[j].w : ov[j].y;
                hp = bfpack(a, b);
                ra = a - __uint_as_float(hp << 16);
                rb = b - __uint_as_float(hp & 0xFFFF0000u);
                lp = bfpack(ra, rb);
                ao32[k>>1] = hp; ao32[32 + (k>>1)] = hp; ao32[64 + (k>>1)] = lp;
            }
        }
        __syncthreads();

        const int nxt = tile + gridDim.x;
        if (nxt < P1_TILES){
            const float4* xp = (const float4*)(x    + (size_t)((long long)nxt*P1_ROWS + cr)*64 + ck0);
            const float4* op = (const float4*)(osrc + (size_t)((long long)nxt*P1_ROWS + cr)*64 + ck0);
            #pragma unroll
            for (int j = 0; j < 4; j++){ xv[j] = xp[j]; ov[j] = op[j]; }
        }

        float acc[4][6][4];
        #pragma unroll
        for (int mi = 0; mi < 4; mi++)
            #pragma unroll
            for (int ni = 0; ni < 6; ni++)
                #pragma unroll
                for (int e = 0; e < 4; e++) acc[mi][ni][e] = 0.0f;

        #pragma unroll
        for (int kf = 0; kf < 12; kf++){
            u32 Axf[4][4], Aof[4][4];
            if (needx){
                #pragma unroll
                for (int mi = 0; mi < 4; mi++)
                    ldsm_x4(Axf[mi][0],Axf[mi][1],Axf[mi][2],Axf[mi][3], rowAx[mi] + kf*32);
            }
            if (needo){
                #pragma unroll
                for (int mi = 0; mi < 4; mi++)
                    ldsm_x4(Aof[mi][0],Aof[mi][1],Aof[mi][2],Aof[mi][3], rowAo[mi] + kf*32);
            }
            u32 Bf[6][2];
            #pragma unroll
            for (int ni = 0; ni < 6; ni++)
                ldsm_x2(Bf[ni][0], Bf[ni][1], rowB[ni] + kf*32);

            #pragma unroll
            for (int ni = 0; ni < 6; ni++){
                const bool isx = (48*w + 8*ni) < 256;
                #pragma unroll
                for (int mi = 0; mi < 4; mi++)
                    mma16816(acc[mi][ni], isx ? Axf[mi] : Aof[mi], Bf[ni]);
            }
        }
        __syncthreads();

        #pragma unroll
        for (int mi = 0; mi < 4; mi++){
            #pragma unroll
            for (int half = 0; half < 2; half++){
                int r = 16*mi + gid + 8*half;
                long long m = m0 + r;
                u32 mu = (u32)m;
                u32 qq = mu / NN;
                u32 n  = mu - qq*NN;
                u32 t  = qq % NT, b = qq / NT;
                size_t ro = (size_t)t*NROWS + (size_t)b*NN + n;
                float* pAG = g_AG + ro*384;
                #pragma unroll
                for (int ni = 0; ni < 6; ni++){
                    int col = 48*w + 8*ni + 2*tid4;
                    float2 bv = *(const float2*)&bias_s[col];
                    float2 cv;
                    cv.x = acc[mi][ni][half*2 + 0] + bv.x;
                    cv.y = acc[mi][ni][half*2 + 1] + bv.y;
                    *(float2*)(pAG + col) = cv;
                }
            }
        }
        tile = nxt;
    }
}

// =====================================================================
// Phase 2: half-pipelined HMMA recurrence, gate-aligned fragments.
// 130 blocks x 40 rows: half A = rows 0-23 (2 m16 tiles, pad 32),
// half B = rows 24-39 (1 tile, buffer rows 32-47).
// Slot s: MMA(half s&1, t=s>>1) issue, then EW(other half, prev slot)
// on already-drained accumulators -> MUFU overlaps tensor drain.
// All gates register-resident; ONE __syncthreads per slot.
// =====================================================================
#define P2_THREADS 256
#define P2_R 40
#define P2_BLOCKS 130
#define HPITCH 272                   // bytes per h/B row (hi 128 | lo 128 + pad)
#define SB_B   0                     // 384*272 = 104448
#define SB_H   104448                // 48*272 = 13056
#define P2_SMEM (104448 + 13056)     // 117504

template<int MI>
__device__ __forceinline__ void mma_tiles(float acc[][6][4], const u32* rowA,
                                          const u32* rowB){
    #pragma unroll
    for (int kf = 0; kf < 4; kf++){
        u32 Ah[MI][4], Al[MI][4];
        #pragma unroll
        for (int mi = 0; mi < MI; mi++){
            ldsm_x4(Ah[mi][0],Ah[mi][1],Ah[mi][2],Ah[mi][3], rowA[mi] + kf*32);
            ldsm_x4(Al[mi][0],Al[mi][1],Al[mi][2],Al[mi][3], rowA[mi] + 128 + kf*32);
        }
        u32 Bh[6][2], Bl[6][2];
        #pragma unroll
        for (int g = 0; g < 6; g++){
            ldsm_x2(Bh[g][0], Bh[g][1], rowB[g] + kf*32);
            ldsm_x2(Bl[g][0], Bl[g][1], rowB[g] + 128 + kf*32);
        }
        #pragma unroll
        for (int g = 0; g < 6; g++)
            #pragma unroll
            for (int mi = 0; mi < MI; mi++){
                mma16816(acc[mi][g], Ah[mi], Bh[g]);
                mma16816(acc[mi][g], Ah[mi], Bl[g]);
                mma16816(acc[mi][g], Al[mi], Bh[g]);
            }
    }
}

// one element-pair LSTM update from 12 gate scalars
__device__ __forceinline__ void lstm_pair(
    float gf0, float gi0, float go0, float gu0, float gG0, float gV0,
    float gf1, float gi1, float go1, float gu1, float gG1, float gV1,
    float& c0, float& c1, float& hn0, float& hn1)
{
    {
        float ef = __expf(-gf0);
        float eg = __expf(-gG0);
        float fgf = __fdividef(1.0f, 1.0f + ef + eg + ef*eg);
        float ei = __expf(-gi0);
        float eu = __expf(-gu0);
        float ev = __expf(-gV0);
        float iuu = __fdividef(1.0f, (1.0f+ei)*(1.0f+eu)*(1.0f+ev));
        float c = fgf*c0 + iuu;
        c0 = c;
        float ot = __fdividef(1.0f, 1.0f + __expf(-go0));
        float th = 1.0f - __fdividef(2.0f, 1.0f + __expf(2.0f*c));
        hn0 = ot * th;
    }
    {
        float ef = __expf(-gf1);
        float eg = __expf(-gG1);
        float fgf = __fdividef(1.0f, 1.0f + ef + eg + ef*eg);
        float ei = __expf(-gi1);
        float eu = __expf(-gu1);
        float ev = __expf(-gV1);
        float iuu = __fdividef(1.0f, (1.0f+ei)*(1.0f+eu)*(1.0f+ev));
        float c = fgf*c1 + iuu;
        c1 = c;
        float ot = __fdividef(1.0f, 1.0f + __expf(-go1));
        float th = 1.0f - __fdividef(2.0f, 1.0f + __expf(2.0f*c));
        hn1 = ot * th;
    }
}

__global__ void __launch_bounds__(P2_THREADS, 1)
glstm_rec_mma(const float* __restrict__ Vx, const float* __restrict__ Vg,
              float* __restrict__ hidden, float* __restrict__ htp, float* __restrict__ ctp)
{
    extern __shared__ unsigned char smem[];
    const u32 sb = smem_u32(smem);

    const int tid  = threadIdx.x;
    const int lane = tid & 31;
    const int w    = tid >> 5;      // 0..7
    const int gid  = lane >> 2, tid4 = lane & 3;
    const int blk  = blockIdx.x;
    const int hcol = 8*w + 2*tid4;  // h column pair owned by this thread
    const int hpi  = 4*w + tid4;

    // ---- build fused B = [Vx | Vg] rows n=0..383 as [hi(64)|lo(64)] bf16 ----
    for (int i = tid; i < 64*384; i += P2_THREADS){
        int k = i / 384, n = i - k*384;
        float v = (n < 256) ? Vx[k*256 + n] : Vg[k*128 + (n - 256)];
        __nv_bfloat16 hb = __float2bfloat16(v);
        __nv_bfloat16* row = (__nv_bfloat16*)(smem + SB_B + n*HPITCH);
        row[k]      = hb;
        row[64 + k] = __float2bfloat16(v - __bfloat162float(hb));
    }
    // ---- zero h buffer (48 rows incl. pads) ----
    for (int i = tid; i < 13056/4; i += P2_THREADS)
        ((u32*)(smem + SB_H))[i] = 0;

    // B ldmatrix addresses: gate g -> rows 64g + 8w .. +7
    u32 rowB[6];
    #pragma unroll
    for (int g = 0; g < 6; g++)
        rowB[g] = sb + SB_B + (u32)(64*g + 8*w + (lane & 7))*HPITCH
                + (((lane >> 3) & 1) << 4);

    // A ldmatrix bases: tiles 0,1 (half A), 2 (half B)
    u32 rowA[3];
    #pragma unroll
    for (int mi = 0; mi < 3; mi++)
        rowA[mi] = sb + SB_H + (u32)(16*mi + (lane & 15))*HPITCH + ((lane >> 4) << 4);

    // half A: rg 0..2 -> buffer row 8rg+gid, global row blk*40 + 8rg+gid
    int rhoA_[3], gbA[3], fbA[3];
    float cA0[3], cA1[3];
    #pragma unroll
    for (int rg = 0; rg < 3; rg++){
        int rho = blk*P2_R + 8*rg + gid;
        rhoA_[rg] = rho;
        int b = rho / NN, n = rho - b*NN;
        gbA[rg] = b*BSTRIDE + n*NH + hcol;
        fbA[rg] = rho*NH + hcol;
        cA0[rg] = 0.0f; cA1[rg] = 0.0f;
    }
    // half B: rg 0..1 -> buffer row 32+8rg+gid, global row blk*40 + 24+8rg+gid
    int rhoB_[2], gbB[2], fbB[2];
    float cB0[2], cB1[2];
    #pragma unroll
    for (int rg = 0; rg < 2; rg++){
        int rho = blk*P2_R + 24 + 8*rg + gid;
        rhoB_[rg] = rho;
        int b = rho / NN, n = rho - b*NN;
        gbB[rg] = b*BSTRIDE + n*NH + hcol;
        fbB[rg] = rho*NH + hcol;
        cB0[rg] = 0.0f; cB1[rg] = 0.0f;
    }
    __syncthreads();

    // ---- prefetch apre t=0 for both halves ----
    float2 apA[3][6], apB[2][6];
    #pragma unroll
    for (int rg = 0; rg < 3; rg++){
        const float* p = g_AG + (size_t)rhoA_[rg]*384 + hcol;
        #pragma unroll
        for (int g = 0; g < 6; g++) apA[rg][g] = *(const float2*)(p + 64*g);
    }
    #pragma unroll
    for (int rg = 0; rg < 2; rg++){
        const float* p = g_AG + (size_t)rhoB_[rg]*384 + hcol;
        #pragma unroll
        for (int g = 0; g < 6; g++) apB[rg][g] = *(const float2*)(p + 64*g);
    }

    float accA[2][6][4], accB[1][6][4];

    for (int s = 0; s <= 2*NT; s++){
        // ---- MMA(half s&1, t = s>>1) ----
        if (s < 2*NT){
            const int tX = s >> 1;
            if ((s & 1) == 0){
                // init accA from apA (tile1 hm=1 is pad -> 0)
                #pragma unroll
                for (int g = 0; g < 6; g++){
                    accA[0][g][0] = apA[0][g].x; accA[0][g][1] = apA[0][g].y;
                    accA[0][g][2] = apA[1][g].x; accA[0][g][3] = apA[1][g].y;
                    accA[1][g][0] = apA[2][g].x; accA[1][g][1] = apA[2][g].y;
                    accA[1][g][2] = 0.0f;        accA[1][g][3] = 0.0f;
                }
                if (tX + 1 < NT){
                    #pragma unroll
                    for (int rg = 0; rg < 3; rg++){
                        const float* p = g_AG + ((size_t)(tX+1)*NROWS + rhoA_[rg])*384 + hcol;
                        #pragma unroll
                        for (int g = 0; g < 6; g++) apA[rg][g] = *(const float2*)(p + 64*g);
                    }
                }
                mma_tiles<2>(accA, rowA, rowB);
            } else {
                #pragma unroll
                for (int g = 0; g < 6; g++){
                    accB[0][g][0] = apB[0][g].x; accB[0][g][1] = apB[0][g].y;
                    accB[0][g][2] = apB[1][g].x; accB[0][g][3] = apB[1][g].y;
                }
                if (tX + 1 < NT){
                    #pragma unroll
                    for (int rg = 0; rg < 2; rg++){
                        const float* p = g_AG + ((size_t)(tX+1)*NROWS + rhoB_[rg])*384 + hcol;
                        #pragma unroll
                        for (int g = 0; g < 6; g++) apB[rg][g] = *(const float2*)(p + 64*g);
                    }
                }
                mma_tiles<1>(accB, rowA + 2, rowB);
            }
        }

        // ---- EW(other half, t = (s-1)>>1) on drained accumulators ----
        if (s > 0){
            const int tY = (s - 1) >> 1;
            if (((s - 1) & 1) == 0){
                // half A: rg 0..2 -> (mi, hm) = (0,0),(0,1),(1,0)
                #pragma unroll
                for (int rg = 0; rg < 3; rg++){
                    int mi = rg >> 1, hm = rg & 1;
                    float hn0, hn1;
                    lstm_pair(accA[mi][0][2*hm], accA[mi][1][2*hm], accA[mi][2][2*hm],
                              accA[mi][3][2*hm], accA[mi][4][2*hm], accA[mi][5][2*hm],
                              accA[mi][0][2*hm+1], accA[mi][1][2*hm+1], accA[mi][2][2*hm+1],
                              accA[mi][3][2*hm+1], accA[mi][4][2*hm+1], accA[mi][5][2*hm+1],
                              cA0[rg], cA1[rg], hn0, hn1);
                    u32 hhi = bfpack(hn0, hn1);
                    float r0 = hn0 - __uint_as_float(hhi << 16);
                    float r1 = hn1 - __uint_as_float(hhi & 0xFFFF0000u);
                    u32 hlo = bfpack(r0, r1);
                    int r = 8*rg + gid;
                    *(u32*)(smem + SB_H + r*HPITCH + 4*hpi)       = hhi;
                    *(u32*)(smem + SB_H + r*HPITCH + 128 + 4*hpi) = hlo;
                    float2 hv = make_float2(hn0, hn1);
                    *(float2*)&hidden[gbA[rg] + tY*HSTRIDE] = hv;
                    if (tY == NT-1){
                        *(float2*)&htp[fbA[rg]] = hv;
                        *(float2*)&ctp[fbA[rg]] = make_float2(cA0[rg], cA1[rg]);
                    }
                }
            } else {
                // half B: rg 0..1 -> (mi=0, hm=rg), buffer rows 32+8rg+gid
                #pragma unroll
                for (int rg = 0; rg < 2; rg++){
                    float hn0, hn1;
                    lstm_pair(accB[0][0][2*rg], accB[0][1][2*rg], accB[0][2][2*rg],
                              accB[0][3][2*rg], accB[0][4][2*rg], accB[0][5][2*rg],
                              accB[0][0][2*rg+1], accB[0][1][2*rg+1], accB[0][2][2*rg+1],
                              accB[0][3][2*rg+1], accB[0][4][2*rg+1], accB[0][5][2*rg+1],
                              cB0[rg], cB1[rg], hn0, hn1);
                    u32 hhi = bfpack(hn0, hn1);
                    float r0 = hn0 - __uint_as_float(hhi << 16);
                    float r1 = hn1 - __uint_as_float(hhi & 0xFFFF0000u);
                    u32 hlo = bfpack(r0, r1);
                    int r = 32 + 8*rg + gid;
                    *(u32*)(smem + SB_H + r*HPITCH + 4*hpi)       = hhi;
                    *(u32*)(smem + SB_H + r*HPITCH + 128 + 4*hpi) = hlo;
                    float2 hv = make_float2(hn0, hn1);
                    *(float2*)&hidden[gbB[rg] + tY*HSTRIDE] = hv;
                    if (tY == NT-1){
                        *(float2*)&htp[fbB[rg]] = hv;
                        *(float2*)&ctp[fbB[rg]] = make_float2(cB0[rg], cB1[rg]);
                    }
                }
            }
        }
        __syncthreads();   // slot boundary: h(Y,tY) published; MMA reads done
    }
}

extern "C" void kernel_launch(void* const* d_in, const int* in_sizes, int n_in,
                              void* d_out, int out_size)
{
    const float* x   = (const float*)d_in[0];
    const float* o_s = (const float*)d_in[1];
    const float* Ux  = (const float*)d_in[2];
    const float* Vx  = (const float*)d_in[3];
    const float* bx  = (const float*)d_in[4];
    const float* Ug  = (const float*)d_in[5];
    const float* Vg  = (const float*)d_in[6];
    const float* bg  = (const float*)d_in[7];

    float* out    = (float*)d_out;
    float* hidden = out;                               // [B,T,N,H]
    float* htp    = out + (size_t)BTN * NH;            // [B,N,H]
    float* ctp    = htp + (size_t)NROWS * NH;          // [B,N,H]

    cudaFuncSetAttribute(glstm_pre_mma, cudaFuncAttributeMaxDynamicSharedMemorySize, P1_SMEM);
    cudaFuncSetAttribute(glstm_rec_mma, cudaFuncAttributeMaxDynamicSharedMemorySize, P2_SMEM);

    glstm_pre_mma<<<P1_GRID, P1_THREADS, P1_SMEM>>>(x, o_s, Ux, bx, Ug, bg);
    glstm_rec_mma<<<P2_BLOCKS, P2_THREADS, P2_SMEM>>>(Vx, Vg, hidden, htp, ctp);
}